// round 8
// baseline (speedup 1.0000x reference)
#include <cuda_runtime.h>
#include <cstdint>

#define D_MODEL 1024
#define N_HEADS 16
#define DK      64
#define SEQ     2048
#define BATCH   2
#define ROWS    (BATCH * SEQ)          /* 4096 */
#define BH      (BATCH * N_HEADS)      /* 32 */
#define LN_EPS  1e-5f

#define SY ((long long)ROWS * D_MODEL)                         /* 4194304  */
#define SA ((long long)BH * SEQ * SEQ)                         /* 134217728 */

// ---------------- scratch (static device globals: no runtime alloc) --------
__device__ float g_q  [ROWS * D_MODEL];
__device__ float g_k  [ROWS * D_MODEL];
__device__ float g_v  [ROWS * D_MODEL];
__device__ float g_ctx[ROWS * D_MODEL];
__device__ float g_o  [ROWS * D_MODEL];
__device__ float g_xr [ROWS * D_MODEL];               // tf32-rounded x
__device__ float g_wr [4 * D_MODEL * D_MODEL];        // tf32-rounded Wq,Wk,Wv,Wo
__device__ float g_sc [(size_t)BH * SEQ * SEQ];       // attn fallback buffer
__device__ float g_l  [BH * SEQ];                     // row sums of exp

// ---------------- helpers --------------------------------------------------
__device__ __forceinline__ float tf32r(float f) {
    uint32_t u;
    asm("cvt.rna.tf32.f32 %0, %1;" : "=r"(u) : "f"(f));
    return __uint_as_float(u);
}
__device__ __forceinline__ uint32_t tf32bits(float f) {
    uint32_t u;
    asm("cvt.rna.tf32.f32 %0, %1;" : "=r"(u) : "f"(f));
    return u;
}
// operands pre-rounded: raw bits are exact tf32
__device__ __forceinline__ uint32_t bits(float f) { return __float_as_uint(f); }

__device__ __forceinline__ void cp16(void* smem, const void* g) {
    uint32_t a = (uint32_t)__cvta_generic_to_shared(smem);
    asm volatile("cp.async.cg.shared.global [%0], [%1], 16;" :: "r"(a), "l"(g));
}
#define CP_COMMIT()  asm volatile("cp.async.commit_group;")
#define CP_WAIT(n)   asm volatile("cp.async.wait_group %0;" :: "n"(n))

__device__ __forceinline__ void mma_tf32(float c[4],
    uint32_t a0, uint32_t a1, uint32_t a2, uint32_t a3,
    uint32_t b0, uint32_t b1)
{
    asm volatile(
        "mma.sync.aligned.m16n8k8.row.col.f32.tf32.tf32.f32 "
        "{%0,%1,%2,%3}, {%4,%5,%6,%7}, {%8,%9}, {%0,%1,%2,%3};"
        : "+f"(c[0]), "+f"(c[1]), "+f"(c[2]), "+f"(c[3])
        : "r"(a0), "r"(a1), "r"(a2), "r"(a3), "r"(b0), "r"(b1));
}

__device__ __forceinline__ float warpReduceSum(float v) {
#pragma unroll
    for (int o = 16; o > 0; o >>= 1) v += __shfl_xor_sync(0xffffffffu, v, o);
    return v;
}
__device__ __forceinline__ float blockReduceSum(float v) {
    __shared__ float sh[8];
    __shared__ float res;
    int lane = threadIdx.x & 31, w = threadIdx.x >> 5;
    v = warpReduceSum(v);
    if (lane == 0) sh[w] = v;
    __syncthreads();
    if (w == 0) {
        float t = (lane < 8) ? sh[lane] : 0.0f;
        t = warpReduceSum(t);
        if (lane == 0) res = t;
    }
    __syncthreads();
    float r = res;
    __syncthreads();
    return r;
}

// ---------------- tf32-RNA rounding copy -----------------------------------
__global__ void __launch_bounds__(256)
round_copy4(const float4* __restrict__ src, float4* __restrict__ dst, int n4)
{
    for (int i = blockIdx.x * blockDim.x + threadIdx.x; i < n4;
         i += gridDim.x * blockDim.x) {
        float4 v = src[i];
        v.x = tf32r(v.x); v.y = tf32r(v.y); v.z = tf32r(v.z); v.w = tf32r(v.w);
        dst[i] = v;
    }
}

// ---------------- tf32 GEMM NT core ---------------------------------------
// EXPSTATS: compute exp(alpha*acc) row sums -> atomics to lbuf; no C stores.
// RNDOUT: round outputs to tf32 (for raw consumption downstream).
template<int BN, bool EXPSTATS, bool RNDOUT>
__device__ __forceinline__ void gemm_nt_core(
    const float* __restrict__ A, int lda,
    const float* __restrict__ B, int ldb,
    float* __restrict__ C, int ldc, int K, float alpha,
    float* __restrict__ lbuf)
{
    constexpr int BM  = 128;
    constexpr int BK  = 16;
    constexpr int STR = 20;
    constexpr int TNW = BN / 4;
    constexpr int TNT = BN / 32;

    __shared__ float As[2][BM * STR];
    __shared__ float Bs[2][BN * STR];

    int t    = threadIdx.x;
    int w    = t >> 5, lane = t & 31;
    int wm   = w >> 2, wn = w & 3;
    int g    = lane >> 2, tg = lane & 3;

    const float* Ag = A + (long long)(blockIdx.y * BM) * lda;
    const float* Bg = B + (long long)(blockIdx.x * BN) * ldb;

    int lr = t >> 2;
    int lc = (t & 3) * 4;

    float acc[4][TNT][4];
#pragma unroll
    for (int i = 0; i < 4; i++)
#pragma unroll
        for (int j = 0; j < TNT; j++)
#pragma unroll
            for (int q = 0; q < 4; q++) acc[i][j][q] = 0.0f;

    auto load_tile = [&](int kt, int s) {
        long long ko = (long long)kt * BK;
        cp16(&As[s][lr * STR + lc],        Ag + (long long)lr * lda + ko + lc);
        cp16(&As[s][(lr + 64) * STR + lc], Ag + (long long)(lr + 64) * lda + ko + lc);
        cp16(&Bs[s][lr * STR + lc],        Bg + (long long)lr * ldb + ko + lc);
        if (BN == 128)
            cp16(&Bs[s][(lr + 64) * STR + lc], Bg + (long long)(lr + 64) * ldb + ko + lc);
    };

    int KT = K / BK;
    load_tile(0, 0);
    CP_COMMIT();

    for (int kt = 0; kt < KT; kt++) {
        if (kt + 1 < KT) load_tile(kt + 1, (kt + 1) & 1);
        CP_COMMIT();
        CP_WAIT(1);
        __syncthreads();

        const float* as = As[kt & 1];
        const float* bs = Bs[kt & 1];

#pragma unroll
        for (int kh = 0; kh < 2; kh++) {
            int kk = kh * 8;
            uint32_t af[4][4];
#pragma unroll
            for (int i = 0; i < 4; i++) {
                int r = wm * 64 + i * 16 + g;
                af[i][0] = bits(as[r * STR + kk + tg]);
                af[i][1] = bits(as[(r + 8) * STR + kk + tg]);
                af[i][2] = bits(as[r * STR + kk + tg + 4]);
                af[i][3] = bits(as[(r + 8) * STR + kk + tg + 4]);
            }
            uint32_t bf[TNT][2];
#pragma unroll
            for (int j = 0; j < TNT; j++) {
                int n = wn * TNW + j * 8 + g;
                bf[j][0] = bits(bs[n * STR + kk + tg]);
                bf[j][1] = bits(bs[n * STR + kk + tg + 4]);
            }
#pragma unroll
            for (int i = 0; i < 4; i++)
#pragma unroll
                for (int j = 0; j < TNT; j++)
                    mma_tf32(acc[i][j], af[i][0], af[i][1], af[i][2], af[i][3],
                             bf[j][0], bf[j][1]);
        }
        __syncthreads();
    }

#pragma unroll
    for (int i = 0; i < 4; i++) {
        int rl0 = blockIdx.y * BM + wm * 64 + i * 16 + g;
        long long r0 = rl0;
        if (EXPSTATS) {
            float s0 = 0.0f, s1 = 0.0f;
#pragma unroll
            for (int j = 0; j < TNT; j++) {
                s0 += __expf(alpha * acc[i][j][0]) + __expf(alpha * acc[i][j][1]);
                s1 += __expf(alpha * acc[i][j][2]) + __expf(alpha * acc[i][j][3]);
            }
            s0 += __shfl_xor_sync(0xffffffffu, s0, 1);
            s0 += __shfl_xor_sync(0xffffffffu, s0, 2);
            s1 += __shfl_xor_sync(0xffffffffu, s1, 1);
            s1 += __shfl_xor_sync(0xffffffffu, s1, 2);
            if (tg == 0) {
                atomicAdd(&lbuf[rl0],     s0);
                atomicAdd(&lbuf[rl0 + 8], s1);
            }
        } else {
#pragma unroll
            for (int j = 0; j < TNT; j++) {
                int col = blockIdx.x * BN + wn * TNW + j * 8 + tg * 2;
                float v0 = alpha * acc[i][j][0], v1 = alpha * acc[i][j][1];
                float v2 = alpha * acc[i][j][2], v3 = alpha * acc[i][j][3];
                if (RNDOUT) { v0 = tf32r(v0); v1 = tf32r(v1); v2 = tf32r(v2); v3 = tf32r(v3); }
                *(float2*)(C + r0 * ldc + col)       = make_float2(v0, v1);
                *(float2*)(C + (r0 + 8) * ldc + col) = make_float2(v2, v3);
            }
        }
    }
}

// ---------------- projection kernels ---------------------------------------
__global__ void __launch_bounds__(256)
qkv_proj(const float* __restrict__ xr, const float* __restrict__ wr,
         float* __restrict__ q, float* __restrict__ k, float* __restrict__ v)
{
    const float* B = wr + (long long)blockIdx.z * D_MODEL * D_MODEL;
    float*       C = (blockIdx.z == 0) ? q : (blockIdx.z == 1) ? k : v;
    gemm_nt_core<128, false, true>(xr, D_MODEL, B, D_MODEL, C, D_MODEL,
                                   D_MODEL, 1.0f, nullptr);
}

__global__ void __launch_bounds__(256)
out_proj(const float* __restrict__ ctx, const float* __restrict__ wr,
         float* __restrict__ o)
{
    gemm_nt_core<128, false, false>(ctx, D_MODEL, wr + 3LL * D_MODEL * D_MODEL,
                                    D_MODEL, o, D_MODEL, D_MODEL, 1.0f, nullptr);
}

// ---------------- stats: l[row] = sum exp(QK^T/8) (no score stores) --------
__global__ void __launch_bounds__(256)
scores_stats(const float* __restrict__ q, const float* __restrict__ k,
             float* __restrict__ l)
{
    int z = blockIdx.z, zb = z >> 4, zh = z & 15;
    const long long SBH = (long long)SEQ * D_MODEL;
    gemm_nt_core<128, true, false>(
        q + (long long)zb * SBH + (long long)zh * DK, D_MODEL,
        k + (long long)zb * SBH + (long long)zh * DK, D_MODEL,
        nullptr, 0, DK, 0.125f,
        l + (long long)z * SEQ);
}

// ---------------- fused attention: recompute S, emit attn, ctx = P@V -------
// Block = 128 q-rows of one head; stream K/V in 64-row tiles (32 iterations).
// smem ~105 KB -> 2 CTAs/SM. All operands pre-rounded tf32 except P (cvt at
// PV A-fragment load: 32 cvts/warp/tile).
#define ASTR 68
#define AC_SMEM ((128*ASTR + 64*ASTR + 64*ASTR + 128*ASTR + 128) * 4)

__global__ void __launch_bounds__(256)
attn_ctx(const float* __restrict__ Qg, const float* __restrict__ Kg,
         const float* __restrict__ Vg, const float* __restrict__ lsum,
         float* __restrict__ attn, float* __restrict__ ctx)
{
    extern __shared__ float sm[];
    float* Qs   = sm;                      // 128 x 68
    float* Ks   = Qs + 128 * ASTR;         // 64 x 68
    float* Vs   = Ks + 64 * ASTR;          // 64 x 68
    float* Ps   = Vs + 64 * ASTR;          // 128 x 68
    float* invl = Ps + 128 * ASTR;         // 128

    int bh = blockIdx.y, b = bh >> 4, h = bh & 15;
    int q0 = blockIdx.x * 128;
    const float* qb = Qg + (long long)b * SEQ * D_MODEL + h * DK;
    const float* kb = Kg + (long long)b * SEQ * D_MODEL + h * DK;
    const float* vb = Vg + (long long)b * SEQ * D_MODEL + h * DK;
    float* at_b = attn + ((long long)bh * SEQ + q0) * SEQ;

    int t = threadIdx.x, w = t >> 5, lane = t & 31;
    int g = lane >> 2, tg = lane & 3;
    int wrow = w * 16;
    int r0 = wrow + g, r1 = wrow + g + 8;

    // Q tile 128x64
#pragma unroll
    for (int i = t; i < 2048; i += 256) {
        int r = i >> 4, c4 = (i & 15) * 4;
        cp16(&Qs[r * ASTR + c4], qb + (long long)(q0 + r) * D_MODEL + c4);
    }
    CP_COMMIT();
    if (t < 128) invl[t] = 1.0f / lsum[(long long)bh * SEQ + q0 + t];
    CP_WAIT(0);
    __syncthreads();

    float iv0 = invl[r0], iv1 = invl[r1];

    float d[8][4];
#pragma unroll
    for (int j = 0; j < 8; j++)
#pragma unroll
        for (int q = 0; q < 4; q++) d[j][q] = 0.0f;

    for (int kt = 0; kt < 32; kt++) {
        int s0 = kt * 64;
        // K,V tiles 64x64 each
#pragma unroll
        for (int i = t; i < 1024; i += 256) {
            int r = i >> 4, c4 = (i & 15) * 4;
            cp16(&Ks[r * ASTR + c4], kb + (long long)(s0 + r) * D_MODEL + c4);
            cp16(&Vs[r * ASTR + c4], vb + (long long)(s0 + r) * D_MODEL + c4);
        }
        CP_COMMIT();
        CP_WAIT(0);
        __syncthreads();

        // S = Q(strip) @ K^T : c[8][4]
        float c[8][4];
#pragma unroll
        for (int j = 0; j < 8; j++)
#pragma unroll
            for (int q = 0; q < 4; q++) c[j][q] = 0.0f;
#pragma unroll
        for (int ks = 0; ks < 8; ks++) {
            int k0 = ks * 8;
            uint32_t a0 = bits(Qs[r0 * ASTR + k0 + tg]);
            uint32_t a1 = bits(Qs[r1 * ASTR + k0 + tg]);
            uint32_t a2 = bits(Qs[r0 * ASTR + k0 + tg + 4]);
            uint32_t a3 = bits(Qs[r1 * ASTR + k0 + tg + 4]);
#pragma unroll
            for (int j = 0; j < 8; j++) {
                int n = j * 8 + g;
                uint32_t b0 = bits(Ks[n * ASTR + k0 + tg]);
                uint32_t b1 = bits(Ks[n * ASTR + k0 + tg + 4]);
                mma_tf32(c[j], a0, a1, a2, a3, b0, b1);
            }
        }

        // p = exp(s/8) * invl ; stage into Ps (unrounded)
#pragma unroll
        for (int j = 0; j < 8; j++) {
            c[j][0] = __expf(c[j][0] * 0.125f) * iv0;
            c[j][1] = __expf(c[j][1] * 0.125f) * iv0;
            c[j][2] = __expf(c[j][2] * 0.125f) * iv1;
            c[j][3] = __expf(c[j][3] * 0.125f) * iv1;
            int col = j * 8 + 2 * tg;
            *(float2*)&Ps[r0 * ASTR + col] = make_float2(c[j][0], c[j][1]);
            *(float2*)&Ps[r1 * ASTR + col] = make_float2(c[j][2], c[j][3]);
        }
        __syncthreads();

        // attn tile out (coalesced from Ps)
#pragma unroll
        for (int i = t; i < 2048; i += 256) {
            int r = i >> 4, c4 = (i & 15) * 4;
            __stcs((float4*)(at_b + (long long)r * SEQ + s0 + c4),
                   *(const float4*)&Ps[r * ASTR + c4]);
        }

        // ctx += P @ V  (A = Ps needs rounding; V pre-rounded)
#pragma unroll
        for (int ks = 0; ks < 8; ks++) {
            int k0 = ks * 8;
            uint32_t a0 = tf32bits(Ps[r0 * ASTR + k0 + tg]);
            uint32_t a1 = tf32bits(Ps[r1 * ASTR + k0 + tg]);
            uint32_t a2 = tf32bits(Ps[r0 * ASTR + k0 + tg + 4]);
            uint32_t a3 = tf32bits(Ps[r1 * ASTR + k0 + tg + 4]);
#pragma unroll
            for (int j = 0; j < 8; j++) {
                uint32_t b0 = bits(Vs[(k0 + tg) * ASTR + j * 8 + g]);
                uint32_t b1 = bits(Vs[(k0 + tg + 4) * ASTR + j * 8 + g]);
                mma_tf32(d[j], a0, a1, a2, a3, b0, b1);
            }
        }
        __syncthreads();   // before next tile overwrites Ks/Vs/Ps
    }

    // ctx epilogue (rounded: out_proj consumes raw bits)
    float* cb = ctx + ((long long)b * SEQ + q0) * D_MODEL + h * DK;
#pragma unroll
    for (int j = 0; j < 8; j++) {
        int col = j * 8 + 2 * tg;
        *(float2*)(cb + (long long)r0 * D_MODEL + col) =
            make_float2(tf32r(d[j][0]), tf32r(d[j][1]));
        *(float2*)(cb + (long long)r1 * D_MODEL + col) =
            make_float2(tf32r(d[j][2]), tf32r(d[j][3]));
    }
}

// ---------------- bias + residual + LayerNorm ------------------------------
__global__ void __launch_bounds__(256)
bias_res_ln(const float* __restrict__ o, const float* __restrict__ x,
            const float* __restrict__ bo, const float* __restrict__ gamma,
            const float* __restrict__ beta, float* __restrict__ y)
{
    long long row = blockIdx.x;
    int tid = threadIdx.x;
    const float4* o4 = (const float4*)(o + row * D_MODEL);
    const float4* x4 = (const float4*)(x + row * D_MODEL);
    const float4* b4 = (const float4*)bo;
    const float4* g4 = (const float4*)gamma;
    const float4* be4 = (const float4*)beta;

    float4 ov = o4[tid], xv = x4[tid], bv = b4[tid];
    float4 v;
    v.x = ov.x + xv.x + bv.x;
    v.y = ov.y + xv.y + bv.y;
    v.z = ov.z + xv.z + bv.z;
    v.w = ov.w + xv.w + bv.w;

    float s  = v.x + v.y + v.z + v.w;
    float sq = v.x * v.x + v.y * v.y + v.z * v.z + v.w * v.w;
    s  = blockReduceSum(s);
    sq = blockReduceSum(sq);

    float mean = s * (1.0f / D_MODEL);
    float var  = sq * (1.0f / D_MODEL) - mean * mean;
    float rstd = rsqrtf(var + LN_EPS);

    float4 gv = g4[tid], bev = be4[tid];
    float4 r;
    r.x = (v.x - mean) * rstd * gv.x + bev.x;
    r.y = (v.y - mean) * rstd * gv.y + bev.y;
    r.z = (v.z - mean) * rstd * gv.z + bev.z;
    r.w = (v.w - mean) * rstd * gv.w + bev.w;
    ((float4*)(y + row * D_MODEL))[tid] = r;
}

// ---------------- launch ---------------------------------------------------
extern "C" void kernel_launch(void* const* d_in, const int* in_sizes, int n_in,
                              void* d_out, int out_size)
{
    const float* x     = (const float*)d_in[0];
    const float* Wq    = (const float*)d_in[1];
    const float* Wk    = (const float*)d_in[2];
    const float* Wv    = (const float*)d_in[3];
    const float* Wo    = (const float*)d_in[4];
    const float* bo    = (const float*)d_in[5];
    const float* gamma = (const float*)d_in[6];
    const float* beta  = (const float*)d_in[7];

    float* y_out    = (float*)d_out;
    float* attn_out = nullptr;
    if ((long long)out_size >= SY + SA) {
        attn_out = y_out + SY;                 // outputs concatenated: y, attn
    } else if ((long long)out_size == SA) {
        attn_out = y_out;                      // attn-only output
        y_out = nullptr;
    }

    float *q, *k, *v, *ctx, *ob, *xr, *wr, *sc, *lptr;
    cudaGetSymbolAddress((void**)&q,    g_q);
    cudaGetSymbolAddress((void**)&k,    g_k);
    cudaGetSymbolAddress((void**)&v,    g_v);
    cudaGetSymbolAddress((void**)&ctx,  g_ctx);
    cudaGetSymbolAddress((void**)&ob,   g_o);
    cudaGetSymbolAddress((void**)&xr,   g_xr);
    cudaGetSymbolAddress((void**)&wr,   g_wr);
    cudaGetSymbolAddress((void**)&sc,   g_sc);
    cudaGetSymbolAddress((void**)&lptr, g_l);

    float* attn = attn_out ? attn_out : sc;

    static int smem_set = 0;
    if (!smem_set) {
        cudaFuncSetAttribute(attn_ctx,
            cudaFuncAttributeMaxDynamicSharedMemorySize, AC_SMEM);
        smem_set = 1;
    }

    const int WN4 = D_MODEL * D_MODEL / 4;

    cudaMemsetAsync(lptr, 0, (size_t)BH * SEQ * sizeof(float));

    // pre-round x + weights to tf32-RNA
    round_copy4<<<1024, 256>>>((const float4*)x,  (float4*)xr, (int)(SY / 4));
    round_copy4<<<512, 256>>>((const float4*)Wq, (float4*)(wr + 0LL * D_MODEL * D_MODEL), WN4);
    round_copy4<<<512, 256>>>((const float4*)Wk, (float4*)(wr + 1LL * D_MODEL * D_MODEL), WN4);
    round_copy4<<<512, 256>>>((const float4*)Wv, (float4*)(wr + 2LL * D_MODEL * D_MODEL), WN4);
    round_copy4<<<512, 256>>>((const float4*)Wo, (float4*)(wr + 3LL * D_MODEL * D_MODEL), WN4);

    // Q/K/V projections (rounded outputs)
    qkv_proj<<<dim3(8, 32, 3), 256>>>(xr, wr, q, k, v);

    // row sums only (no 512 MB score store)
    scores_stats<<<dim3(16, 16, BH), 256>>>(q, k, lptr);

    // recompute S, emit normalized attn once, accumulate ctx = P @ V
    attn_ctx<<<dim3(16, BH), 256, AC_SMEM>>>(q, k, v, lptr, attn, ctx);

    if (y_out) {
        out_proj<<<dim3(8, 32), 256>>>(ctx, wr, ob);
        bias_res_ln<<<ROWS, 256>>>(ob, x, bo, gamma, beta, y_out);
    }
}

// round 9
// speedup vs baseline: 1.1545x; 1.1545x over previous
#include <cuda_runtime.h>
#include <cstdint>

#define D_MODEL 1024
#define N_HEADS 16
#define DK      64
#define SEQ     2048
#define BATCH   2
#define ROWS    (BATCH * SEQ)          /* 4096 */
#define BH      (BATCH * N_HEADS)      /* 32 */
#define LN_EPS  1e-5f

#define SY ((long long)ROWS * D_MODEL)                         /* 4194304  */
#define SA ((long long)BH * SEQ * SEQ)                         /* 134217728 */

// ---------------- scratch (static device globals: no runtime alloc) --------
__device__ float g_q  [ROWS * D_MODEL];
__device__ float g_k  [ROWS * D_MODEL];   // reused as V^T after scores GEMM
__device__ float g_v  [ROWS * D_MODEL];
__device__ float g_ctx[ROWS * D_MODEL];
__device__ float g_o  [ROWS * D_MODEL];
__device__ float g_xr [ROWS * D_MODEL];               // tf32-rounded x
__device__ float g_wr [4 * D_MODEL * D_MODEL];        // tf32-rounded weights
__device__ float g_sc [(size_t)BH * SEQ * SEQ];       // rounded exp-scores
__device__ float g_l  [BH * SEQ];                     // row sums of exp

// ---------------- helpers --------------------------------------------------
__device__ __forceinline__ float tf32r(float f) {
    uint32_t u;
    asm("cvt.rna.tf32.f32 %0, %1;" : "=r"(u) : "f"(f));
    return __uint_as_float(u);
}
// operands pre-rounded: raw bits are exact tf32
__device__ __forceinline__ uint32_t bits(float f) { return __float_as_uint(f); }

__device__ __forceinline__ void cp16(void* smem, const void* g) {
    uint32_t a = (uint32_t)__cvta_generic_to_shared(smem);
    asm volatile("cp.async.cg.shared.global [%0], [%1], 16;" :: "r"(a), "l"(g));
}
#define CP_COMMIT()  asm volatile("cp.async.commit_group;")
#define CP_WAIT(n)   asm volatile("cp.async.wait_group %0;" :: "n"(n))

__device__ __forceinline__ void mma_tf32(float c[4],
    uint32_t a0, uint32_t a1, uint32_t a2, uint32_t a3,
    uint32_t b0, uint32_t b1)
{
    asm volatile(
        "mma.sync.aligned.m16n8k8.row.col.f32.tf32.tf32.f32 "
        "{%0,%1,%2,%3}, {%4,%5,%6,%7}, {%8,%9}, {%0,%1,%2,%3};"
        : "+f"(c[0]), "+f"(c[1]), "+f"(c[2]), "+f"(c[3])
        : "r"(a0), "r"(a1), "r"(a2), "r"(a3), "r"(b0), "r"(b1));
}

__device__ __forceinline__ float warpReduceSum(float v) {
#pragma unroll
    for (int o = 16; o > 0; o >>= 1) v += __shfl_xor_sync(0xffffffffu, v, o);
    return v;
}
__device__ __forceinline__ float blockReduceSum(float v) {
    __shared__ float sh[8];
    __shared__ float res;
    int lane = threadIdx.x & 31, w = threadIdx.x >> 5;
    v = warpReduceSum(v);
    if (lane == 0) sh[w] = v;
    __syncthreads();
    if (w == 0) {
        float t = (lane < 8) ? sh[lane] : 0.0f;
        t = warpReduceSum(t);
        if (lane == 0) res = t;
    }
    __syncthreads();
    float r = res;
    __syncthreads();
    return r;
}

// ---------------- merged tf32-RNA rounding (x + 4 weights, one launch) -----
#define NX4 ((int)(SY / 4))                 /* 1048576 */
#define NW4 (D_MODEL * D_MODEL / 4)         /* 262144  */
__global__ void __launch_bounds__(256)
round_all(const float4* __restrict__ x,
          const float4* __restrict__ Wq, const float4* __restrict__ Wk,
          const float4* __restrict__ Wv, const float4* __restrict__ Wo,
          float4* __restrict__ xr, float4* __restrict__ wr)
{
    int n4 = NX4 + 4 * NW4;
    for (int i = blockIdx.x * blockDim.x + threadIdx.x; i < n4;
         i += gridDim.x * blockDim.x) {
        const float4* src;
        float4* dst;
        if (i < NX4) { src = x + i; dst = xr + i; }
        else {
            int j = i - NX4;
            int ws = j / NW4, off = j - ws * NW4;
            src = (ws == 0 ? Wq : ws == 1 ? Wk : ws == 2 ? Wv : Wo) + off;
            dst = wr + (long long)ws * NW4 + off;
        }
        float4 v = *src;
        v.x = tf32r(v.x); v.y = tf32r(v.y); v.z = tf32r(v.z); v.w = tf32r(v.w);
        *dst = v;
    }
}

// ---------------- tf32 GEMM NT core ---------------------------------------
// EXPOUT: store tf32r(exp(alpha*acc)) + per-row exp-sum atomics to lbuf.
// RNDOUT: round outputs (raw-bit consumption downstream).
template<int BN, bool EXPOUT, bool RNDOUT>
__device__ __forceinline__ void gemm_nt_core(
    const float* __restrict__ A, int lda,
    const float* __restrict__ B, int ldb,
    float* __restrict__ C, int ldc, int K, float alpha,
    float* __restrict__ lbuf)
{
    constexpr int BM  = 128;
    constexpr int BK  = 16;
    constexpr int STR = 20;
    constexpr int TNW = BN / 4;
    constexpr int TNT = BN / 32;

    __shared__ float As[2][BM * STR];
    __shared__ float Bs[2][BN * STR];

    int t    = threadIdx.x;
    int w    = t >> 5, lane = t & 31;
    int wm   = w >> 2, wn = w & 3;
    int g    = lane >> 2, tg = lane & 3;

    const float* Ag = A + (long long)(blockIdx.y * BM) * lda;
    const float* Bg = B + (long long)(blockIdx.x * BN) * ldb;

    int lr = t >> 2;
    int lc = (t & 3) * 4;

    float acc[4][TNT][4];
#pragma unroll
    for (int i = 0; i < 4; i++)
#pragma unroll
        for (int j = 0; j < TNT; j++)
#pragma unroll
            for (int q = 0; q < 4; q++) acc[i][j][q] = 0.0f;

    auto load_tile = [&](int kt, int s) {
        long long ko = (long long)kt * BK;
        cp16(&As[s][lr * STR + lc],        Ag + (long long)lr * lda + ko + lc);
        cp16(&As[s][(lr + 64) * STR + lc], Ag + (long long)(lr + 64) * lda + ko + lc);
        cp16(&Bs[s][lr * STR + lc],        Bg + (long long)lr * ldb + ko + lc);
        if (BN == 128)
            cp16(&Bs[s][(lr + 64) * STR + lc], Bg + (long long)(lr + 64) * ldb + ko + lc);
    };

    int KT = K / BK;
    load_tile(0, 0);
    CP_COMMIT();

    for (int kt = 0; kt < KT; kt++) {
        if (kt + 1 < KT) load_tile(kt + 1, (kt + 1) & 1);
        CP_COMMIT();
        CP_WAIT(1);
        __syncthreads();

        const float* as = As[kt & 1];
        const float* bs = Bs[kt & 1];

#pragma unroll
        for (int kh = 0; kh < 2; kh++) {
            int kk = kh * 8;
            uint32_t af[4][4];
#pragma unroll
            for (int i = 0; i < 4; i++) {
                int r = wm * 64 + i * 16 + g;
                af[i][0] = bits(as[r * STR + kk + tg]);
                af[i][1] = bits(as[(r + 8) * STR + kk + tg]);
                af[i][2] = bits(as[r * STR + kk + tg + 4]);
                af[i][3] = bits(as[(r + 8) * STR + kk + tg + 4]);
            }
            uint32_t bf[TNT][2];
#pragma unroll
            for (int j = 0; j < TNT; j++) {
                int n = wn * TNW + j * 8 + g;
                bf[j][0] = bits(bs[n * STR + kk + tg]);
                bf[j][1] = bits(bs[n * STR + kk + tg + 4]);
            }
#pragma unroll
            for (int i = 0; i < 4; i++)
#pragma unroll
                for (int j = 0; j < TNT; j++)
                    mma_tf32(acc[i][j], af[i][0], af[i][1], af[i][2], af[i][3],
                             bf[j][0], bf[j][1]);
        }
        __syncthreads();
    }

#pragma unroll
    for (int i = 0; i < 4; i++) {
        int rl0 = blockIdx.y * BM + wm * 64 + i * 16 + g;
        long long r0 = rl0;
        if (EXPOUT) {
            float s0 = 0.0f, s1 = 0.0f;
#pragma unroll
            for (int j = 0; j < TNT; j++) {
                float e0 = __expf(alpha * acc[i][j][0]);
                float e1 = __expf(alpha * acc[i][j][1]);
                float e2 = __expf(alpha * acc[i][j][2]);
                float e3 = __expf(alpha * acc[i][j][3]);
                int col = blockIdx.x * BN + wn * TNW + j * 8 + tg * 2;
                __stcs((float2*)(C + r0 * ldc + col),
                       make_float2(tf32r(e0), tf32r(e1)));
                __stcs((float2*)(C + (r0 + 8) * ldc + col),
                       make_float2(tf32r(e2), tf32r(e3)));
                s0 += e0 + e1;
                s1 += e2 + e3;
            }
            s0 += __shfl_xor_sync(0xffffffffu, s0, 1);
            s0 += __shfl_xor_sync(0xffffffffu, s0, 2);
            s1 += __shfl_xor_sync(0xffffffffu, s1, 1);
            s1 += __shfl_xor_sync(0xffffffffu, s1, 2);
            if (tg == 0) {
                atomicAdd(&lbuf[rl0],     s0);
                atomicAdd(&lbuf[rl0 + 8], s1);
            }
        } else {
#pragma unroll
            for (int j = 0; j < TNT; j++) {
                int col = blockIdx.x * BN + wn * TNW + j * 8 + tg * 2;
                float v0 = alpha * acc[i][j][0], v1 = alpha * acc[i][j][1];
                float v2 = alpha * acc[i][j][2], v3 = alpha * acc[i][j][3];
                if (RNDOUT) { v0 = tf32r(v0); v1 = tf32r(v1); v2 = tf32r(v2); v3 = tf32r(v3); }
                *(float2*)(C + r0 * ldc + col)       = make_float2(v0, v1);
                *(float2*)(C + (r0 + 8) * ldc + col) = make_float2(v2, v3);
            }
        }
    }
}

// ---------------- projection kernels ---------------------------------------
__global__ void __launch_bounds__(256)
qkv_proj(const float* __restrict__ xr, const float* __restrict__ wr,
         float* __restrict__ q, float* __restrict__ k, float* __restrict__ v)
{
    const float* B = wr + (long long)blockIdx.z * D_MODEL * D_MODEL;
    float*       C = (blockIdx.z == 0) ? q : (blockIdx.z == 1) ? k : v;
    gemm_nt_core<128, false, true>(xr, D_MODEL, B, D_MODEL, C, D_MODEL,
                                   D_MODEL, 1.0f, nullptr);
}

__global__ void __launch_bounds__(256)
out_proj(const float* __restrict__ ctx, const float* __restrict__ wr,
         float* __restrict__ o)
{
    gemm_nt_core<128, false, false>(ctx, D_MODEL, wr + 3LL * D_MODEL * D_MODEL,
                                    D_MODEL, o, D_MODEL, D_MODEL, 1.0f, nullptr);
}

// ---------------- scores: tf32r(exp(QK^T/8)) + row sums --------------------
__global__ void __launch_bounds__(256)
scores_exp(const float* __restrict__ q, const float* __restrict__ k,
           float* __restrict__ sc, float* __restrict__ l)
{
    int z = blockIdx.z, zb = z >> 4, zh = z & 15;
    const long long SBH = (long long)SEQ * D_MODEL;
    gemm_nt_core<128, true, false>(
        q + (long long)zb * SBH + (long long)zh * DK, D_MODEL,
        k + (long long)zb * SBH + (long long)zh * DK, D_MODEL,
        sc + (long long)z * SEQ * SEQ, SEQ,
        DK, 0.125f,
        l + (long long)z * SEQ);
}

// ---------------- per-head V transpose: Vt[bh][d][s] -----------------------
__global__ void __launch_bounds__(256)
transpose_v(const float* __restrict__ v, float* __restrict__ vt)
{
    __shared__ float tile[32][33];
    int bh = blockIdx.z;
    int b = bh >> 4, h = bh & 15;
    int s0 = blockIdx.x * 32, d0 = blockIdx.y * 32;
    int tx = threadIdx.x, ty = threadIdx.y;

    const float* src = v + (long long)b * SEQ * D_MODEL + h * DK;
#pragma unroll
    for (int i = ty; i < 32; i += 8)
        tile[i][tx] = src[(long long)(s0 + i) * D_MODEL + d0 + tx];
    __syncthreads();
    float* dst = vt + (long long)bh * DK * SEQ;
#pragma unroll
    for (int i = ty; i < 32; i += 8)
        dst[(long long)(d0 + i) * SEQ + s0 + tx] = tile[tx][i];   // already tf32
}

// ---------------- fused: attn emit + ctx GEMM (fully async A path) ---------
// ctx_row = (sum_j expP_ij * v_j) * invl_row  (normalization decoupled).
// 64-col chunks, double-buffered cp.async for A (exp-scores) and B (Vt).
// smem: As[2][128x68] Bs[2][64x68] invl[128] = 104,960 B -> 2 CTAs/SM.
#define FSTR 68
#define FC_SMEM ((2 * 128 * FSTR + 2 * 64 * FSTR + 128) * 4)

__global__ void __launch_bounds__(256)
fused_ctx(const float* __restrict__ expsc, const float* __restrict__ lsum,
          const float* __restrict__ vt, float* __restrict__ attn,
          float* __restrict__ ctx)
{
    extern __shared__ float sm[];
    float* As0  = sm;                       // 128 x 68
    float* As1  = As0 + 128 * FSTR;
    float* Bs0  = As1 + 128 * FSTR;         // 64 x 68
    float* Bs1  = Bs0 + 64 * FSTR;
    float* invl = Bs1 + 64 * FSTR;          // 128

    int bh = blockIdx.y, b = bh >> 4, h = bh & 15;
    int q0 = blockIdx.x * 128;

    const float* sc_b = expsc + ((long long)bh * SEQ + q0) * SEQ;
    const float* vt_b = vt + (long long)bh * DK * SEQ;
    float* at_b = attn + ((long long)bh * SEQ + q0) * SEQ;

    int t = threadIdx.x, w = t >> 5, lane = t & 31;
    int wm = w >> 2, wn = w & 3;           // 2x4 warps: m64 x n16 warp tiles
    int g = lane >> 2, tg = lane & 3;

    auto loadA = [&](float* dst, int k0) {
#pragma unroll
        for (int i = t; i < 2048; i += 256) {            // 128x64 = 2048 float4
            int r = i >> 4, c4 = (i & 15) * 4;
            cp16(&dst[r * FSTR + c4], sc_b + (long long)r * SEQ + k0 + c4);
        }
    };
    auto loadB = [&](float* dst, int k0) {
#pragma unroll
        for (int i = t; i < 1024; i += 256) {            // 64x64 = 1024 float4
            int r = i >> 4, c4 = (i & 15) * 4;
            cp16(&dst[r * FSTR + c4], vt_b + (long long)r * SEQ + k0 + c4);
        }
    };

    if (t < 128) invl[t] = 1.0f / lsum[(long long)bh * SEQ + q0 + t];

    float acc[4][2][4];
#pragma unroll
    for (int i = 0; i < 4; i++)
#pragma unroll
        for (int j = 0; j < 2; j++)
#pragma unroll
            for (int q = 0; q < 4; q++) acc[i][j][q] = 0.0f;

    loadA(As0, 0);
    loadB(Bs0, 0);
    CP_COMMIT();
    __syncthreads();   // invl visible (cp.async still in flight)

    for (int kt = 0; kt < SEQ / 64; kt++) {
        int k0 = kt * 64;
        float* as = (kt & 1) ? As1 : As0;
        float* bs = (kt & 1) ? Bs1 : Bs0;

        if (kt < SEQ / 64 - 1) {
            loadA((kt & 1) ? As0 : As1, k0 + 64);
            loadB((kt & 1) ? Bs0 : Bs1, k0 + 64);
            CP_COMMIT();
            CP_WAIT(1);
        } else {
            CP_WAIT(0);
        }
        __syncthreads();

        // attn emit first (stores in flight during MMA): p = expP * invl
#pragma unroll
        for (int i = t; i < 2048; i += 256) {
            int r = i >> 4, c4 = (i & 15) * 4;
            float4 p = *(const float4*)&as[r * FSTR + c4];
            float iv = invl[r];
            p.x *= iv; p.y *= iv; p.z *= iv; p.w *= iv;
            __stcs((float4*)(at_b + (long long)r * SEQ + k0 + c4), p);
        }

        // ctx += expP @ Vt^T  (both operands pre-rounded: raw bits)
#pragma unroll
        for (int ks = 0; ks < 8; ks++) {
            int kk = ks * 8;
            uint32_t af[4][4];
#pragma unroll
            for (int i = 0; i < 4; i++) {
                int r = wm * 64 + i * 16 + g;
                af[i][0] = bits(as[r * FSTR + kk + tg]);
                af[i][1] = bits(as[(r + 8) * FSTR + kk + tg]);
                af[i][2] = bits(as[r * FSTR + kk + tg + 4]);
                af[i][3] = bits(as[(r + 8) * FSTR + kk + tg + 4]);
            }
            uint32_t bf[2][2];
#pragma unroll
            for (int j = 0; j < 2; j++) {
                int n = wn * 16 + j * 8 + g;
                bf[j][0] = bits(bs[n * FSTR + kk + tg]);
                bf[j][1] = bits(bs[n * FSTR + kk + tg + 4]);
            }
#pragma unroll
            for (int i = 0; i < 4; i++)
#pragma unroll
                for (int j = 0; j < 2; j++)
                    mma_tf32(acc[i][j], af[i][0], af[i][1], af[i][2], af[i][3],
                             bf[j][0], bf[j][1]);
        }
        __syncthreads();   // before next iteration's cp.async reuses buffers
    }

    // ctx epilogue: scale by invl, round (out_proj consumes raw bits)
    float* cb = ctx + ((long long)b * SEQ + q0) * D_MODEL + h * DK;
#pragma unroll
    for (int i = 0; i < 4; i++) {
        int r = wm * 64 + i * 16 + g;
        float iv0 = invl[r], iv1 = invl[r + 8];
#pragma unroll
        for (int j = 0; j < 2; j++) {
            int col = wn * 16 + j * 8 + tg * 2;
            *(float2*)(cb + (long long)r * D_MODEL + col) =
                make_float2(tf32r(acc[i][j][0] * iv0), tf32r(acc[i][j][1] * iv0));
            *(float2*)(cb + (long long)(r + 8) * D_MODEL + col) =
                make_float2(tf32r(acc[i][j][2] * iv1), tf32r(acc[i][j][3] * iv1));
        }
    }
}

// ---------------- bias + residual + LayerNorm ------------------------------
__global__ void __launch_bounds__(256)
bias_res_ln(const float* __restrict__ o, const float* __restrict__ x,
            const float* __restrict__ bo, const float* __restrict__ gamma,
            const float* __restrict__ beta, float* __restrict__ y)
{
    long long row = blockIdx.x;
    int tid = threadIdx.x;
    const float4* o4 = (const float4*)(o + row * D_MODEL);
    const float4* x4 = (const float4*)(x + row * D_MODEL);
    const float4* b4 = (const float4*)bo;
    const float4* g4 = (const float4*)gamma;
    const float4* be4 = (const float4*)beta;

    float4 ov = o4[tid], xv = x4[tid], bv = b4[tid];
    float4 v;
    v.x = ov.x + xv.x + bv.x;
    v.y = ov.y + xv.y + bv.y;
    v.z = ov.z + xv.z + bv.z;
    v.w = ov.w + xv.w + bv.w;

    float s  = v.x + v.y + v.z + v.w;
    float sq = v.x * v.x + v.y * v.y + v.z * v.z + v.w * v.w;
    s  = blockReduceSum(s);
    sq = blockReduceSum(sq);

    float mean = s * (1.0f / D_MODEL);
    float var  = sq * (1.0f / D_MODEL) - mean * mean;
    float rstd = rsqrtf(var + LN_EPS);

    float4 gv = g4[tid], bev = be4[tid];
    float4 r;
    r.x = (v.x - mean) * rstd * gv.x + bev.x;
    r.y = (v.y - mean) * rstd * gv.y + bev.y;
    r.z = (v.z - mean) * rstd * gv.z + bev.z;
    r.w = (v.w - mean) * rstd * gv.w + bev.w;
    ((float4*)(y + row * D_MODEL))[tid] = r;
}

// ---------------- launch ---------------------------------------------------
extern "C" void kernel_launch(void* const* d_in, const int* in_sizes, int n_in,
                              void* d_out, int out_size)
{
    const float* x     = (const float*)d_in[0];
    const float* Wq    = (const float*)d_in[1];
    const float* Wk    = (const float*)d_in[2];
    const float* Wv    = (const float*)d_in[3];
    const float* Wo    = (const float*)d_in[4];
    const float* bo    = (const float*)d_in[5];
    const float* gamma = (const float*)d_in[6];
    const float* beta  = (const float*)d_in[7];

    float* y_out    = (float*)d_out;
    float* attn_out = nullptr;
    if ((long long)out_size >= SY + SA) {
        attn_out = y_out + SY;                 // outputs concatenated: y, attn
    } else if ((long long)out_size == SA) {
        attn_out = y_out;                      // attn-only output
        y_out = nullptr;
    }

    float *q, *k, *v, *ctx, *ob, *xr, *wr, *sc, *lptr;
    cudaGetSymbolAddress((void**)&q,    g_q);
    cudaGetSymbolAddress((void**)&k,    g_k);
    cudaGetSymbolAddress((void**)&v,    g_v);
    cudaGetSymbolAddress((void**)&ctx,  g_ctx);
    cudaGetSymbolAddress((void**)&ob,   g_o);
    cudaGetSymbolAddress((void**)&xr,   g_xr);
    cudaGetSymbolAddress((void**)&wr,   g_wr);
    cudaGetSymbolAddress((void**)&sc,   g_sc);
    cudaGetSymbolAddress((void**)&lptr, g_l);

    float* attn = attn_out ? attn_out : sc;    // in-place fallback is safe
    float* vt   = k;                           // V^T reuses K buffer

    static int smem_set = 0;
    if (!smem_set) {
        cudaFuncSetAttribute(fused_ctx,
            cudaFuncAttributeMaxDynamicSharedMemorySize, FC_SMEM);
        smem_set = 1;
    }

    cudaMemsetAsync(lptr, 0, (size_t)BH * SEQ * sizeof(float));

    // pre-round x + all weights (single launch)
    round_all<<<2048, 256>>>((const float4*)x, (const float4*)Wq,
                             (const float4*)Wk, (const float4*)Wv,
                             (const float4*)Wo, (float4*)xr, (float4*)wr);

    // Q/K/V projections (rounded outputs)
    qkv_proj<<<dim3(8, 32, 3), 256>>>(xr, wr, q, k, v);

    // rounded exp-scores + row sums
    scores_exp<<<dim3(16, 16, BH), 256>>>(q, k, sc, lptr);

    // V^T per head (K buffer free after scores)
    transpose_v<<<dim3(SEQ / 32, DK / 32, BH), dim3(32, 8)>>>(v, vt);

    // attn emit + ctx GEMM (async pipelined)
    fused_ctx<<<dim3(16, BH), 256, FC_SMEM>>>(sc, lptr, vt, attn, ctx);

    if (y_out) {
        out_proj<<<dim3(8, 32), 256>>>(ctx, wr, ob);
        bias_res_ln<<<ROWS, 256>>>(ob, x, bo, gamma, beta, y_out);
    }
}